// round 14
// baseline (speedup 1.0000x reference)
#include <cuda_runtime.h>
#include <math.h>

typedef unsigned long long ull;

#define NT 10
#define NL 16
#define NNODES 31
#define BB 4096
#define G4 1024
#define NTHR 512

// lstm smem layout in floats
#define PW 260                       // W row pitch (16B aligned, conflict-free)
#define PR 80                        // sR combo pitch
#define OFF_W 0                      // 64 rows x PW
#define OFF_H (64 * PW)              // 16 warp-stages x 320 (10 combos x 32 k)
#define OFF_R (OFF_H + 16 * 320)     // 8 kslices x 20 combos x PR
#define SMEM_FLOATS (OFF_R + 8 * 20 * PR)
#define SMEM_BYTES (SMEM_FLOATS * 4)

__device__ __align__(16) float g_XGA[310 * G4];   // k-half 0 (+bias)
__device__ __align__(16) float g_XGB[310 * G4];   // k-half 1
__device__ __align__(16) float g_H[2][160 * 256];
__device__ int g_src[BB * NT];                    // per-row float4 offset into H
__device__ unsigned g_flag[8 * 16 * 32];          // [cy][dx], 128B-strided

__device__ __forceinline__ float sigf(float x) { return 1.0f / (1.0f + __expf(-x)); }

__device__ __forceinline__ void fma2(ull& d, ull a, ull b) {
    asm("fma.rn.f32x2 %0, %1, %2, %0;" : "+l"(d) : "l"(a), "l"(b));
}
__device__ __forceinline__ float sum2(ull v) {
    float2 f = *(float2*)&v;
    return f.x + f.y;
}
__device__ __forceinline__ unsigned atom_add_release(unsigned* p, unsigned v) {
    unsigned r;
    asm volatile("atom.release.gpu.global.add.u32 %0, [%1], %2;"
                 : "=r"(r) : "l"(p), "r"(v) : "memory");
    return r;
}
__device__ __forceinline__ unsigned ld_acquire(unsigned* p) {
    unsigned r;
    asm volatile("ld.acquire.gpu.global.u32 %0, [%1];"
                 : "=r"(r) : "l"(p) : "memory");
    return r;
}

// ---------------------------------------------------------------------------
// xg: XG[m][j] = emb[m] . W_ih[j] (+ bias on kz=0), K-split in 2 halves.
// Grid (8 colblk x 10 nodeblk x 2 ksplit), 256 thr. (R9/R10-proven)
// ---------------------------------------------------------------------------
#define PE 66          // sE pitch
#define PWX 129        // sW pitch (k-major rows; transpose-store 2-way max)
__global__ void __launch_bounds__(256)
xg_kernel(const float* __restrict__ emb,
          const float* __restrict__ W_ih,
          const float* __restrict__ b_ih,
          const float* __restrict__ b_hh) {
    __shared__ float sE[32 * PE];        // 32 nodes x 64 k
    __shared__ float sW[64 * PWX];       // 64 k x 128 cols
    const int tid = threadIdx.x;
    const int cb = blockIdx.x;
    const int mb = blockIdx.y;
    const int kz = blockIdx.z;
    const int ty = tid >> 5, tx = tid & 31;

    float acc[4][4] = {};

    #pragma unroll
    for (int kc = 0; kc < 2; ++kc) {
        const int k0 = kz * 128 + kc * 64;
        for (int idx = tid; idx < 512; idx += 256) {
            int r = idx >> 4, q = idx & 15;
            int m = mb * 32 + r;
            float4 v = (m < 310)
                     ? *(const float4*)(emb + m * 256 + k0 + q * 4)
                     : make_float4(0.f, 0.f, 0.f, 0.f);
            sE[r * PE + q*4+0] = v.x; sE[r * PE + q*4+1] = v.y;
            sE[r * PE + q*4+2] = v.z; sE[r * PE + q*4+3] = v.w;
        }
        for (int idx = tid; idx < 2048; idx += 256) {
            int cl = idx >> 4, q = idx & 15;
            float4 v = *(const float4*)(W_ih + (cb * 128 + cl) * 256 + k0 + q * 4);
            sW[(q*4+0) * PWX + cl] = v.x;
            sW[(q*4+1) * PWX + cl] = v.y;
            sW[(q*4+2) * PWX + cl] = v.z;
            sW[(q*4+3) * PWX + cl] = v.w;
        }
        __syncthreads();
        #pragma unroll
        for (int k = 0; k < 64; ++k) {
            float e0 = sE[(ty*4+0) * PE + k];
            float e1 = sE[(ty*4+1) * PE + k];
            float e2 = sE[(ty*4+2) * PE + k];
            float e3 = sE[(ty*4+3) * PE + k];
            float w0 = sW[k * PWX + tx];
            float w1 = sW[k * PWX + tx + 32];
            float w2 = sW[k * PWX + tx + 64];
            float w3 = sW[k * PWX + tx + 96];
            acc[0][0] += e0*w0; acc[0][1] += e0*w1; acc[0][2] += e0*w2; acc[0][3] += e0*w3;
            acc[1][0] += e1*w0; acc[1][1] += e1*w1; acc[1][2] += e1*w2; acc[1][3] += e1*w3;
            acc[2][0] += e2*w0; acc[2][1] += e2*w1; acc[2][2] += e2*w2; acc[2][3] += e2*w3;
            acc[3][0] += e3*w0; acc[3][1] += e3*w1; acc[3][2] += e3*w2; acc[3][3] += e3*w3;
        }
        __syncthreads();
    }

    float* dst = kz ? g_XGB : g_XGA;
    #pragma unroll
    for (int i = 0; i < 4; ++i) {
        int m = mb * 32 + ty * 4 + i;
        if (m >= 310) break;
        #pragma unroll
        for (int j = 0; j < 4; ++j) {
            int col = cb * 128 + tx + 32 * j;
            float v = acc[i][j];
            if (kz == 0) v += b_ih[col] + b_hh[col];
            dst[m * G4 + col] = v;
        }
    }
}

// ---------------------------------------------------------------------------
// Persistent LSTM with point-to-point producer/consumer sync (R13-proven).
// Grid (16,8), 512 thr, 1 block/SM.
// ---------------------------------------------------------------------------
__global__ void __launch_bounds__(NTHR, 1)
lstm_kernel(const float* __restrict__ W_hh) {
    extern __shared__ __align__(16) float sm[];
    float* sW = sm + OFF_W;
    float* sh = sm + OFF_H;
    float* sR = sm + OFF_R;

    const int tid = threadIdx.x;
    const int dx = blockIdx.x;      // 0..15
    const int cy = blockIdx.y;      // 0..7
    const int d0 = dx << 4;

    // Cache W_hh slice: row r: j = (r>>4)*256 + d0 + (r&15), k = 0..255.
    for (int i = tid; i < 4096; i += NTHR) {
        int row = i >> 6, q = i & 63;
        int j = ((row >> 4) << 8) + d0 + (row & 15);
        *(float4*)(sW + row * PW + q * 4) = ((const float4*)W_hh)[j * 64 + q];
    }

    const int lc = tid >> 4, dl = tid & 15;
    const int c = cy * 20 + lc;
    const int d = d0 + dl;
    const int tree = c >> 4, leaf = c & 15;
    unsigned* myflag = &g_flag[(cy * 16 + dx) * 32];

    // ---- Step 0 (h0 = c0 = 0) ----
    float cst = 0.f;
    if (tid < 320) {
        const float* xa = g_XGA + (tree * NNODES) * G4;
        const float* xb = g_XGB + (tree * NNODES) * G4;
        float gi = __ldg(xa + d)       + __ldg(xb + d);
        float gg = __ldg(xa + 512 + d) + __ldg(xb + 512 + d);
        float go = __ldg(xa + 768 + d) + __ldg(xb + 768 + d);
        cst = sigf(gi) * tanhf(gg);
        float h = sigf(go) * tanhf(cst);
        __stcg(&g_H[0][c * 256 + d], h);
    }
    __syncthreads();
    if (tid == 0) atom_add_release(myflag, 1);   // h generation 1 available

    const int w = tid >> 5, lane = tid & 31;
    const int cs = w & 1;            // combo half: combos cs*10..+9
    const int ks = w >> 1;           // K slice: k = ks*32..+31 (8 slices)
    const float* Wra = sW + lane * PW + ks * 32;
    const float* Wrb = sW + (lane + 32) * PW + ks * 32;
    float* hstage = sh + (cs * 8 + ks) * 320;    // warp-private h stage
    float* rb = sR + ks * (20 * PR) + cs * 10 * PR;
    unsigned* pf = &g_flag[(cy * 16 + 2 * ks + (lane & 1)) * 32];  // lanes 0/1 poll

    #pragma unroll
    for (int t = 1; t <= 4; ++t) {
        const int bin = 1 - (t & 1), bout = t & 1;

        // Prefetch this step's XG contribution (independent of h).
        float pa0 = 0.f, pa1 = 0.f, pa2 = 0.f, pa3 = 0.f;
        if (tid < 320) {
            int local = ((1 << t) - 1) + (leaf >> (4 - t));
            const float* xa = g_XGA + (tree * NNODES + local) * G4;
            const float* xb = g_XGB + (tree * NNODES + local) * G4;
            pa0 = __ldg(xa + d)       + __ldg(xb + d);
            pa1 = __ldg(xa + 256 + d) + __ldg(xb + 256 + d);
            pa2 = __ldg(xa + 512 + d) + __ldg(xb + 512 + d);
            pa3 = __ldg(xa + 768 + d) + __ldg(xb + 768 + d);
        }

        // Wait for my 2 producer blocks only, then pull my 10x32 h slice.
        if (lane < 2) {
            while ((int)ld_acquire(pf) < t) {}
        }
        __syncwarp();
        #pragma unroll
        for (int i = 0; i < 10; ++i)
            hstage[i * 32 + lane] =
                __ldcg(&g_H[bin][(cy * 20 + cs * 10 + i) * 256 + ks * 32 + lane]);
        __syncwarp();

        ull accA[10] = {};
        ull accB[10] = {};
        #pragma unroll
        for (int kq = 0; kq < 8; ++kq) {
            ulonglong2 wa = *(const ulonglong2*)(Wra + kq * 4);
            ulonglong2 wb = *(const ulonglong2*)(Wrb + kq * 4);
            #pragma unroll
            for (int i = 0; i < 10; ++i) {
                ulonglong2 hv = *(const ulonglong2*)(hstage + i * 32 + kq * 4);
                fma2(accA[i], wa.x, hv.x); fma2(accA[i], wa.y, hv.y);
                fma2(accB[i], wb.x, hv.x); fma2(accB[i], wb.y, hv.y);
            }
        }
        #pragma unroll
        for (int i = 0; i < 10; ++i) {
            rb[i * PR + lane]      = sum2(accA[i]);
            rb[i * PR + lane + 32] = sum2(accB[i]);
        }
        __syncthreads();

        if (tid < 320) {
            const float* rr = sR + lc * PR + dl;
            float gi = pa0, gf = pa1, gg = pa2, go = pa3;
            #pragma unroll
            for (int kk = 0; kk < 8; ++kk) {
                gi += rr[kk * 1600 +  0];
                gf += rr[kk * 1600 + 16];
                gg += rr[kk * 1600 + 32];
                go += rr[kk * 1600 + 48];
            }
            cst = sigf(gf) * cst + sigf(gi) * tanhf(gg);
            float h = sigf(go) * tanhf(cst);
            __stcg(&g_H[bout][c * 256 + d], h);
        }
        __syncthreads();
        if (t < 4 && tid == 0) atom_add_release(myflag, 1);
    }
}

// ---------------------------------------------------------------------------
// Leaf: per (b,tree) row, find leaf via ballot and precompute the float4
// source offset ((tree%? no: tr<<4 + leaf)*64) for the gather.
// ---------------------------------------------------------------------------
__global__ void leaf_kernel(const float* __restrict__ cross) {
    int gid = blockIdx.x * 256 + threadIdx.x;
    float v = cross[gid];
    unsigned m = __ballot_sync(0xffffffffu, v > 0.5f);
    int lane = threadIdx.x & 31;
    unsigned m16 = (m >> (lane & 16)) & 0xFFFFu;
    if ((lane & 15) == 0) {
        int row = gid >> 4;
        int lf = __ffs(m16) - 1;
        int tr = row - (row / NT) * NT;
        g_src[row] = ((tr << 4) + lf) << 6;      // float4 index into H
    }
}

// ---------------------------------------------------------------------------
// Gather: deep-loop full-residency. Grid 160 x 1024 thr; thread owns
// (q = tid&63, rsub = tid>>6) and loops 16 rows -> 8+ LDG.128 in flight.
// ---------------------------------------------------------------------------
__global__ void __launch_bounds__(1024)
gather_kernel(float4* __restrict__ out) {
    if (blockIdx.x == 0 && threadIdx.x < 128)
        g_flag[threadIdx.x * 32] = 0;            // reset for next graph replay
    const int tid = threadIdx.x;
    const int q = tid & 63;
    const int rsub = tid >> 6;                   // 0..15
    const int base = blockIdx.x * 256;           // 160 blocks x 256 rows
    const float4* H4 = (const float4*)g_H[0];
    #pragma unroll 8
    for (int i = 0; i < 16; ++i) {
        int row = base + i * 16 + rsub;
        int off = __ldg(&g_src[row]);
        out[(size_t)row * 64 + q] = __ldg(H4 + off + q);
    }
}

// ---------------------------------------------------------------------------
extern "C" void kernel_launch(void* const* d_in, const int* in_sizes, int n_in,
                              void* d_out, int out_size) {
    const float* cross = (const float*)d_in[0];
    const float* emb   = (const float*)d_in[1];
    const float* W_ih  = (const float*)d_in[2];
    const float* W_hh  = (const float*)d_in[3];
    const float* b_ih  = (const float*)d_in[4];
    const float* b_hh  = (const float*)d_in[5];

    static int attr_done = 0;
    if (!attr_done) {
        cudaFuncSetAttribute(lstm_kernel,
                             cudaFuncAttributeMaxDynamicSharedMemorySize,
                             SMEM_BYTES);
        attr_done = 1;
    }

    xg_kernel<<<dim3(8, 10, 2), 256>>>(emb, W_ih, b_ih, b_hh);
    leaf_kernel<<<BB * NT * NL / 256, 256>>>(cross);
    lstm_kernel<<<dim3(16, 8), NTHR, SMEM_BYTES>>>(W_hh);
    gather_kernel<<<160, 1024>>>((float4*)d_out);
}

// round 15
// speedup vs baseline: 1.3081x; 1.3081x over previous
#include <cuda_runtime.h>
#include <math.h>

typedef unsigned long long ull;

#define NT 10
#define NL 16
#define NNODES 31
#define BB 4096
#define G4 1024
#define NTHR 512

// lstm smem layout in floats
#define PW 260                       // W row pitch (16B aligned, conflict-free)
#define PR 80                        // sR combo pitch
#define OFF_W 0                      // 64 rows x PW
#define OFF_H (64 * PW)              // 16 warp-stages x 320 (10 combos x 32 k)
#define OFF_R (OFF_H + 16 * 320)     // 8 kslices x 20 combos x PR
#define SMEM_FLOATS (OFF_R + 8 * 20 * PR)
#define SMEM_BYTES (SMEM_FLOATS * 4)

__device__ __align__(16) float g_XG[4][310 * G4]; // K-quarter partials (bias on 0)
__device__ __align__(16) float g_H[2][160 * 256];
__device__ int g_src[BB * NT];                    // per-row float4 offset into H
__device__ unsigned g_flag[8 * 16 * 32];          // [cy][dx], 128B-strided

__device__ __forceinline__ float sigf(float x) { return 1.0f / (1.0f + __expf(-x)); }

__device__ __forceinline__ void fma2(ull& d, ull a, ull b) {
    asm("fma.rn.f32x2 %0, %1, %2, %0;" : "+l"(d) : "l"(a), "l"(b));
}
__device__ __forceinline__ float sum2(ull v) {
    float2 f = *(float2*)&v;
    return f.x + f.y;
}
__device__ __forceinline__ unsigned atom_add_release(unsigned* p, unsigned v) {
    unsigned r;
    asm volatile("atom.release.gpu.global.add.u32 %0, [%1], %2;"
                 : "=r"(r) : "l"(p), "r"(v) : "memory");
    return r;
}
__device__ __forceinline__ unsigned ld_acquire(unsigned* p) {
    unsigned r;
    asm volatile("ld.acquire.gpu.global.u32 %0, [%1];"
                 : "=r"(r) : "l"(p) : "memory");
    return r;
}

// ---------------------------------------------------------------------------
// xg: XG[kz][m][j] = emb[m][kz*64:+64] . W_ih[j][same] (+ bias on kz=0).
// Grid (8 colblk x 10 nodeblk x 4 ksplit) = 320 blocks, 256 thr.
// One 64-k tile per block (half the R13 critical path).
// ---------------------------------------------------------------------------
#define PE 66          // sE pitch
#define PWX 129        // sW pitch (k-major rows; transpose-store 2-way max)
__global__ void __launch_bounds__(256)
xg_kernel(const float* __restrict__ emb,
          const float* __restrict__ W_ih,
          const float* __restrict__ b_ih,
          const float* __restrict__ b_hh) {
    __shared__ float sE[32 * PE];        // 32 nodes x 64 k
    __shared__ float sW[64 * PWX];       // 64 k x 128 cols
    const int tid = threadIdx.x;
    const int cb = blockIdx.x;
    const int mb = blockIdx.y;
    const int kz = blockIdx.z;           // k quarter: k = kz*64..+63
    const int ty = tid >> 5, tx = tid & 31;
    const int k0 = kz * 64;

    float acc[4][4] = {};

    for (int idx = tid; idx < 512; idx += 256) {
        int r = idx >> 4, q = idx & 15;
        int m = mb * 32 + r;
        float4 v = (m < 310)
                 ? *(const float4*)(emb + m * 256 + k0 + q * 4)
                 : make_float4(0.f, 0.f, 0.f, 0.f);
        sE[r * PE + q*4+0] = v.x; sE[r * PE + q*4+1] = v.y;
        sE[r * PE + q*4+2] = v.z; sE[r * PE + q*4+3] = v.w;
    }
    for (int idx = tid; idx < 2048; idx += 256) {
        int cl = idx >> 4, q = idx & 15;
        float4 v = *(const float4*)(W_ih + (cb * 128 + cl) * 256 + k0 + q * 4);
        sW[(q*4+0) * PWX + cl] = v.x;
        sW[(q*4+1) * PWX + cl] = v.y;
        sW[(q*4+2) * PWX + cl] = v.z;
        sW[(q*4+3) * PWX + cl] = v.w;
    }
    __syncthreads();
    #pragma unroll
    for (int k = 0; k < 64; ++k) {
        float e0 = sE[(ty*4+0) * PE + k];
        float e1 = sE[(ty*4+1) * PE + k];
        float e2 = sE[(ty*4+2) * PE + k];
        float e3 = sE[(ty*4+3) * PE + k];
        float w0 = sW[k * PWX + tx];
        float w1 = sW[k * PWX + tx + 32];
        float w2 = sW[k * PWX + tx + 64];
        float w3 = sW[k * PWX + tx + 96];
        acc[0][0] += e0*w0; acc[0][1] += e0*w1; acc[0][2] += e0*w2; acc[0][3] += e0*w3;
        acc[1][0] += e1*w0; acc[1][1] += e1*w1; acc[1][2] += e1*w2; acc[1][3] += e1*w3;
        acc[2][0] += e2*w0; acc[2][1] += e2*w1; acc[2][2] += e2*w2; acc[2][3] += e2*w3;
        acc[3][0] += e3*w0; acc[3][1] += e3*w1; acc[3][2] += e3*w2; acc[3][3] += e3*w3;
    }

    float* dst = g_XG[kz];
    #pragma unroll
    for (int i = 0; i < 4; ++i) {
        int m = mb * 32 + ty * 4 + i;
        if (m >= 310) break;
        #pragma unroll
        for (int j = 0; j < 4; ++j) {
            int col = cb * 128 + tx + 32 * j;
            float v = acc[i][j];
            if (kz == 0) v += b_ih[col] + b_hh[col];
            dst[m * G4 + col] = v;
        }
    }
}

// ---------------------------------------------------------------------------
// Persistent LSTM with point-to-point producer/consumer sync (R13-proven).
// Grid (16,8), 512 thr, 1 block/SM. XG read as sum of 4 K-quarter partials.
// ---------------------------------------------------------------------------
__device__ __forceinline__ float xg4(const int node, const int off) {
    return __ldg(&g_XG[0][node * G4 + off]) + __ldg(&g_XG[1][node * G4 + off])
         + __ldg(&g_XG[2][node * G4 + off]) + __ldg(&g_XG[3][node * G4 + off]);
}

__global__ void __launch_bounds__(NTHR, 1)
lstm_kernel(const float* __restrict__ W_hh) {
    extern __shared__ __align__(16) float sm[];
    float* sW = sm + OFF_W;
    float* sh = sm + OFF_H;
    float* sR = sm + OFF_R;

    const int tid = threadIdx.x;
    const int dx = blockIdx.x;      // 0..15
    const int cy = blockIdx.y;      // 0..7
    const int d0 = dx << 4;

    // Cache W_hh slice: row r: j = (r>>4)*256 + d0 + (r&15), k = 0..255.
    for (int i = tid; i < 4096; i += NTHR) {
        int row = i >> 6, q = i & 63;
        int j = ((row >> 4) << 8) + d0 + (row & 15);
        *(float4*)(sW + row * PW + q * 4) = ((const float4*)W_hh)[j * 64 + q];
    }

    const int lc = tid >> 4, dl = tid & 15;
    const int c = cy * 20 + lc;
    const int d = d0 + dl;
    const int tree = c >> 4, leaf = c & 15;
    unsigned* myflag = &g_flag[(cy * 16 + dx) * 32];

    // ---- Step 0 (h0 = c0 = 0) ----
    float cst = 0.f;
    if (tid < 320) {
        const int node = tree * NNODES;
        float gi = xg4(node, d);
        float gg = xg4(node, 512 + d);
        float go = xg4(node, 768 + d);
        cst = sigf(gi) * tanhf(gg);
        float h = sigf(go) * tanhf(cst);
        __stcg(&g_H[0][c * 256 + d], h);
    }
    __syncthreads();
    if (tid == 0) atom_add_release(myflag, 1);   // h generation 1 available

    const int w = tid >> 5, lane = tid & 31;
    const int cs = w & 1;            // combo half: combos cs*10..+9
    const int ks = w >> 1;           // K slice: k = ks*32..+31 (8 slices)
    const float* Wra = sW + lane * PW + ks * 32;
    const float* Wrb = sW + (lane + 32) * PW + ks * 32;
    float* hstage = sh + (cs * 8 + ks) * 320;    // warp-private h stage
    float* rb = sR + ks * (20 * PR) + cs * 10 * PR;
    unsigned* pf = &g_flag[(cy * 16 + 2 * ks + (lane & 1)) * 32];  // lanes 0/1 poll

    #pragma unroll
    for (int t = 1; t <= 4; ++t) {
        const int bin = 1 - (t & 1), bout = t & 1;

        // Prefetch this step's XG contribution (independent of h).
        float pa0 = 0.f, pa1 = 0.f, pa2 = 0.f, pa3 = 0.f;
        if (tid < 320) {
            int node = tree * NNODES + ((1 << t) - 1) + (leaf >> (4 - t));
            pa0 = xg4(node, d);
            pa1 = xg4(node, 256 + d);
            pa2 = xg4(node, 512 + d);
            pa3 = xg4(node, 768 + d);
        }

        // Wait for my 2 producer blocks only, then pull my 10x32 h slice.
        if (lane < 2) {
            while ((int)ld_acquire(pf) < t) {}
        }
        __syncwarp();
        #pragma unroll
        for (int i = 0; i < 10; ++i)
            hstage[i * 32 + lane] =
                __ldcg(&g_H[bin][(cy * 20 + cs * 10 + i) * 256 + ks * 32 + lane]);
        __syncwarp();

        ull accA[10] = {};
        ull accB[10] = {};
        #pragma unroll
        for (int kq = 0; kq < 8; ++kq) {
            ulonglong2 wa = *(const ulonglong2*)(Wra + kq * 4);
            ulonglong2 wb = *(const ulonglong2*)(Wrb + kq * 4);
            #pragma unroll
            for (int i = 0; i < 10; ++i) {
                ulonglong2 hv = *(const ulonglong2*)(hstage + i * 32 + kq * 4);
                fma2(accA[i], wa.x, hv.x); fma2(accA[i], wa.y, hv.y);
                fma2(accB[i], wb.x, hv.x); fma2(accB[i], wb.y, hv.y);
            }
        }
        #pragma unroll
        for (int i = 0; i < 10; ++i) {
            rb[i * PR + lane]      = sum2(accA[i]);
            rb[i * PR + lane + 32] = sum2(accB[i]);
        }
        __syncthreads();

        if (tid < 320) {
            const float* rr = sR + lc * PR + dl;
            float gi = pa0, gf = pa1, gg = pa2, go = pa3;
            #pragma unroll
            for (int kk = 0; kk < 8; ++kk) {
                gi += rr[kk * 1600 +  0];
                gf += rr[kk * 1600 + 16];
                gg += rr[kk * 1600 + 32];
                go += rr[kk * 1600 + 48];
            }
            cst = sigf(gf) * cst + sigf(gi) * tanhf(gg);
            float h = sigf(go) * tanhf(cst);
            __stcg(&g_H[bout][c * 256 + d], h);
        }
        __syncthreads();
        if (t < 4 && tid == 0) atom_add_release(myflag, 1);
    }
}

// ---------------------------------------------------------------------------
// Leaf: per (b,tree) row, find leaf via ballot and precompute the float4
// source offset into H for the gather.
// ---------------------------------------------------------------------------
__global__ void leaf_kernel(const float* __restrict__ cross) {
    int gid = blockIdx.x * 256 + threadIdx.x;
    float v = cross[gid];
    unsigned m = __ballot_sync(0xffffffffu, v > 0.5f);
    int lane = threadIdx.x & 31;
    unsigned m16 = (m >> (lane & 16)) & 0xFFFFu;
    if ((lane & 15) == 0) {
        int row = gid >> 4;
        int lf = __ffs(m16) - 1;
        int tr = row - (row / NT) * NT;
        g_src[row] = ((tr << 4) + lf) << 6;      // float4 index into H
    }
}

// ---------------------------------------------------------------------------
// Gather: R13-proven wide-grid shape (5120 blocks, 2 float4/thread),
// with precomputed g_src offsets.
// ---------------------------------------------------------------------------
__global__ void gather_kernel(float4* __restrict__ out) {
    if (blockIdx.x == 0 && threadIdx.x < 128)
        g_flag[threadIdx.x * 32] = 0;            // reset for next graph replay
    int gid = blockIdx.x * 256 + threadIdx.x;    // 0..1310719
    int row0 = gid >> 6, q = gid & 63;
    int row1 = row0 + 20480;
    int off0 = __ldg(&g_src[row0]);
    int off1 = __ldg(&g_src[row1]);
    const float4* H4 = (const float4*)g_H[0];
    float4 v0 = __ldg(H4 + off0 + q);
    float4 v1 = __ldg(H4 + off1 + q);
    out[(size_t)row0 * 64 + q] = v0;
    out[(size_t)row1 * 64 + q] = v1;
}

// ---------------------------------------------------------------------------
extern "C" void kernel_launch(void* const* d_in, const int* in_sizes, int n_in,
                              void* d_out, int out_size) {
    const float* cross = (const float*)d_in[0];
    const float* emb   = (const float*)d_in[1];
    const float* W_ih  = (const float*)d_in[2];
    const float* W_hh  = (const float*)d_in[3];
    const float* b_ih  = (const float*)d_in[4];
    const float* b_hh  = (const float*)d_in[5];

    static int attr_done = 0;
    if (!attr_done) {
        cudaFuncSetAttribute(lstm_kernel,
                             cudaFuncAttributeMaxDynamicSharedMemorySize,
                             SMEM_BYTES);
        attr_done = 1;
    }

    xg_kernel<<<dim3(8, 10, 4), 256>>>(emb, W_ih, b_ih, b_hh);
    leaf_kernel<<<BB * NT * NL / 256, 256>>>(cross);
    lstm_kernel<<<dim3(16, 8), NTHR, SMEM_BYTES>>>(W_hh);
    gather_kernel<<<BB * NT * 64 / 512, 256>>>((float4*)d_out);
}

// round 16
// speedup vs baseline: 1.3444x; 1.0278x over previous
#include <cuda_runtime.h>
#include <math.h>

typedef unsigned long long ull;

#define NT 10
#define NL 16
#define NNODES 31
#define BB 4096
#define G4 1024
#define NTHR 512

// lstm smem layout in floats
#define PW 260                       // W row pitch (16B aligned, conflict-free)
#define PR 80                        // sR combo pitch
#define OFF_W 0                      // 64 rows x PW
#define OFF_H (64 * PW)              // 16 warp-stages x 320 (10 combos x 32 k)
#define OFF_R (OFF_H + 16 * 320)     // 8 kslices x 20 combos x PR
#define SMEM_FLOATS (OFF_R + 8 * 20 * PR)
#define SMEM_BYTES (SMEM_FLOATS * 4)

__device__ __align__(16) float g_XG[4][310 * G4]; // K-quarter partials (bias on 0)
__device__ __align__(16) float g_H[2][160 * 256];
__device__ int g_src[BB * NT];                    // per-row float4 offset into H
__device__ unsigned g_flag[8 * 16 * 32];          // [cy][dx], 128B-strided

__device__ __forceinline__ float sigf(float x) { return 1.0f / (1.0f + __expf(-x)); }

__device__ __forceinline__ void fma2(ull& d, ull a, ull b) {
    asm("fma.rn.f32x2 %0, %1, %2, %0;" : "+l"(d) : "l"(a), "l"(b));
}
__device__ __forceinline__ float sum2(ull v) {
    float2 f = *(float2*)&v;
    return f.x + f.y;
}
__device__ __forceinline__ unsigned atom_add_release(unsigned* p, unsigned v) {
    unsigned r;
    asm volatile("atom.release.gpu.global.add.u32 %0, [%1], %2;"
                 : "=r"(r) : "l"(p), "r"(v) : "memory");
    return r;
}
__device__ __forceinline__ unsigned ld_acquire(unsigned* p) {
    unsigned r;
    asm volatile("ld.acquire.gpu.global.u32 %0, [%1];"
                 : "=r"(r) : "l"(p) : "memory");
    return r;
}

// ---------------------------------------------------------------------------
// xg (+fused leaf): z<4 -> XG[kz][m][j] partial GEMM (R15-proven);
// z==4 -> leaf ballot + g_src precompute + flag reset (80 tail blocks).
// Grid (8 x 10 x 5), 256 thr.
// ---------------------------------------------------------------------------
#define PE 66          // sE pitch
#define PWX 129        // sW pitch (k-major rows; transpose-store 2-way max)
__global__ void __launch_bounds__(256)
xg_kernel(const float* __restrict__ emb,
          const float* __restrict__ W_ih,
          const float* __restrict__ b_ih,
          const float* __restrict__ b_hh,
          const float* __restrict__ cross) {
    __shared__ float sE[32 * PE];        // 32 nodes x 64 k
    __shared__ float sW[64 * PWX];       // 64 k x 128 cols
    const int tid = threadIdx.x;
    const int cb = blockIdx.x;
    const int mb = blockIdx.y;
    const int kz = blockIdx.z;
    const int ty = tid >> 5, tx = tid & 31;

    if (kz == 4) {
        // ---- fused leaf: 80 blocks x 256 thr x 32 iters = 655360 elems ----
        const int chunk = mb * 8 + cb;           // 0..79
        if (chunk == 0 && tid < 128) g_flag[tid * 32] = 0;  // reset for lstm
        const int lane = tid & 31;
        #pragma unroll 4
        for (int it = 0; it < 32; ++it) {
            int gid = chunk * 8192 + it * 256 + tid;
            float v = __ldg(&cross[gid]);
            unsigned m = __ballot_sync(0xffffffffu, v > 0.5f);
            unsigned m16 = (m >> (lane & 16)) & 0xFFFFu;
            if ((lane & 15) == 0) {
                int row = gid >> 4;
                int lf = __ffs(m16) - 1;
                int tr = row - (row / NT) * NT;
                g_src[row] = ((tr << 4) + lf) << 6;   // float4 index into H
            }
        }
        return;
    }

    const int k0 = kz * 64;
    float acc[4][4] = {};

    for (int idx = tid; idx < 512; idx += 256) {
        int r = idx >> 4, q = idx & 15;
        int m = mb * 32 + r;
        float4 v = (m < 310)
                 ? *(const float4*)(emb + m * 256 + k0 + q * 4)
                 : make_float4(0.f, 0.f, 0.f, 0.f);
        sE[r * PE + q*4+0] = v.x; sE[r * PE + q*4+1] = v.y;
        sE[r * PE + q*4+2] = v.z; sE[r * PE + q*4+3] = v.w;
    }
    for (int idx = tid; idx < 2048; idx += 256) {
        int cl = idx >> 4, q = idx & 15;
        float4 v = *(const float4*)(W_ih + (cb * 128 + cl) * 256 + k0 + q * 4);
        sW[(q*4+0) * PWX + cl] = v.x;
        sW[(q*4+1) * PWX + cl] = v.y;
        sW[(q*4+2) * PWX + cl] = v.z;
        sW[(q*4+3) * PWX + cl] = v.w;
    }
    __syncthreads();
    #pragma unroll
    for (int k = 0; k < 64; ++k) {
        float e0 = sE[(ty*4+0) * PE + k];
        float e1 = sE[(ty*4+1) * PE + k];
        float e2 = sE[(ty*4+2) * PE + k];
        float e3 = sE[(ty*4+3) * PE + k];
        float w0 = sW[k * PWX + tx];
        float w1 = sW[k * PWX + tx + 32];
        float w2 = sW[k * PWX + tx + 64];
        float w3 = sW[k * PWX + tx + 96];
        acc[0][0] += e0*w0; acc[0][1] += e0*w1; acc[0][2] += e0*w2; acc[0][3] += e0*w3;
        acc[1][0] += e1*w0; acc[1][1] += e1*w1; acc[1][2] += e1*w2; acc[1][3] += e1*w3;
        acc[2][0] += e2*w0; acc[2][1] += e2*w1; acc[2][2] += e2*w2; acc[2][3] += e2*w3;
        acc[3][0] += e3*w0; acc[3][1] += e3*w1; acc[3][2] += e3*w2; acc[3][3] += e3*w3;
    }

    float* dst = g_XG[kz];
    #pragma unroll
    for (int i = 0; i < 4; ++i) {
        int m = mb * 32 + ty * 4 + i;
        if (m >= 310) break;
        #pragma unroll
        for (int j = 0; j < 4; ++j) {
            int col = cb * 128 + tx + 32 * j;
            float v = acc[i][j];
            if (kz == 0) v += b_ih[col] + b_hh[col];
            dst[m * G4 + col] = v;
        }
    }
}

// ---------------------------------------------------------------------------
// Persistent LSTM with P2P sync (R13-proven core). Grid (16,8), 512 thr.
// PDL: W-load runs overlapped with xg tail; cudaGridDependencySynchronize()
// gates the first g_XG / g_flag access.
// ---------------------------------------------------------------------------
__device__ __forceinline__ float xg4(const int node, const int off) {
    return __ldg(&g_XG[0][node * G4 + off]) + __ldg(&g_XG[1][node * G4 + off])
         + __ldg(&g_XG[2][node * G4 + off]) + __ldg(&g_XG[3][node * G4 + off]);
}

__global__ void __launch_bounds__(NTHR, 1)
lstm_kernel(const float* __restrict__ W_hh) {
    extern __shared__ __align__(16) float sm[];
    float* sW = sm + OFF_W;
    float* sh = sm + OFF_H;
    float* sR = sm + OFF_R;

    const int tid = threadIdx.x;
    const int dx = blockIdx.x;      // 0..15
    const int cy = blockIdx.y;      // 0..7
    const int d0 = dx << 4;

    // Cache W_hh slice (input only — safe before the PDL sync point).
    for (int i = tid; i < 4096; i += NTHR) {
        int row = i >> 6, q = i & 63;
        int j = ((row >> 4) << 8) + d0 + (row & 15);
        *(float4*)(sW + row * PW + q * 4) = ((const float4*)W_hh)[j * 64 + q];
    }

    cudaGridDependencySynchronize();   // wait for xg (+leaf/flag-reset)

    const int lc = tid >> 4, dl = tid & 15;
    const int c = cy * 20 + lc;
    const int d = d0 + dl;
    const int tree = c >> 4, leaf = c & 15;
    unsigned* myflag = &g_flag[(cy * 16 + dx) * 32];

    // ---- Step 0 (h0 = c0 = 0) ----
    float cst = 0.f;
    if (tid < 320) {
        const int node = tree * NNODES;
        float gi = xg4(node, d);
        float gg = xg4(node, 512 + d);
        float go = xg4(node, 768 + d);
        cst = sigf(gi) * tanhf(gg);
        float h = sigf(go) * tanhf(cst);
        __stcg(&g_H[0][c * 256 + d], h);
    }
    __syncthreads();
    if (tid == 0) atom_add_release(myflag, 1);   // h generation 1 available

    const int w = tid >> 5, lane = tid & 31;
    const int cs = w & 1;            // combo half: combos cs*10..+9
    const int ks = w >> 1;           // K slice: k = ks*32..+31 (8 slices)
    const float* Wra = sW + lane * PW + ks * 32;
    const float* Wrb = sW + (lane + 32) * PW + ks * 32;
    float* hstage = sh + (cs * 8 + ks) * 320;    // warp-private h stage
    float* rb = sR + ks * (20 * PR) + cs * 10 * PR;
    unsigned* pf = &g_flag[(cy * 16 + 2 * ks + (lane & 1)) * 32];  // lanes 0/1 poll

    #pragma unroll
    for (int t = 1; t <= 4; ++t) {
        const int bin = 1 - (t & 1), bout = t & 1;

        // Prefetch this step's XG contribution (independent of h).
        float pa0 = 0.f, pa1 = 0.f, pa2 = 0.f, pa3 = 0.f;
        if (tid < 320) {
            int node = tree * NNODES + ((1 << t) - 1) + (leaf >> (4 - t));
            pa0 = xg4(node, d);
            pa1 = xg4(node, 256 + d);
            pa2 = xg4(node, 512 + d);
            pa3 = xg4(node, 768 + d);
        }

        // Wait for my 2 producer blocks only, then pull my 10x32 h slice.
        if (lane < 2) {
            while ((int)ld_acquire(pf) < t) {}
        }
        __syncwarp();
        #pragma unroll
        for (int i = 0; i < 10; ++i)
            hstage[i * 32 + lane] =
                __ldcg(&g_H[bin][(cy * 20 + cs * 10 + i) * 256 + ks * 32 + lane]);
        __syncwarp();

        ull accA[10] = {};
        ull accB[10] = {};
        #pragma unroll
        for (int kq = 0; kq < 8; ++kq) {
            ulonglong2 wa = *(const ulonglong2*)(Wra + kq * 4);
            ulonglong2 wb = *(const ulonglong2*)(Wrb + kq * 4);
            #pragma unroll
            for (int i = 0; i < 10; ++i) {
                ulonglong2 hv = *(const ulonglong2*)(hstage + i * 32 + kq * 4);
                fma2(accA[i], wa.x, hv.x); fma2(accA[i], wa.y, hv.y);
                fma2(accB[i], wb.x, hv.x); fma2(accB[i], wb.y, hv.y);
            }
        }
        #pragma unroll
        for (int i = 0; i < 10; ++i) {
            rb[i * PR + lane]      = sum2(accA[i]);
            rb[i * PR + lane + 32] = sum2(accB[i]);
        }
        __syncthreads();

        if (tid < 320) {
            const float* rr = sR + lc * PR + dl;
            float gi = pa0, gf = pa1, gg = pa2, go = pa3;
            #pragma unroll
            for (int kk = 0; kk < 8; ++kk) {
                gi += rr[kk * 1600 +  0];
                gf += rr[kk * 1600 + 16];
                gg += rr[kk * 1600 + 32];
                go += rr[kk * 1600 + 48];
            }
            cst = sigf(gf) * cst + sigf(gi) * tanhf(gg);
            float h = sigf(go) * tanhf(cst);
            __stcg(&g_H[bout][c * 256 + d], h);
        }
        __syncthreads();
        if (t < 4 && tid == 0) atom_add_release(myflag, 1);
    }
}

// ---------------------------------------------------------------------------
// Gather: R15-proven shape (5120 blocks, 2 float4/thread, g_src offsets).
// PDL-gated on lstm completion.
// ---------------------------------------------------------------------------
__global__ void gather_kernel(float4* __restrict__ out) {
    cudaGridDependencySynchronize();   // wait for lstm
    int gid = blockIdx.x * 256 + threadIdx.x;    // 0..1310719
    int row0 = gid >> 6, q = gid & 63;
    int row1 = row0 + 20480;
    int off0 = __ldg(&g_src[row0]);
    int off1 = __ldg(&g_src[row1]);
    const float4* H4 = (const float4*)g_H[0];
    float4 v0 = __ldg(H4 + off0 + q);
    float4 v1 = __ldg(H4 + off1 + q);
    out[(size_t)row0 * 64 + q] = v0;
    out[(size_t)row1 * 64 + q] = v1;
}

// ---------------------------------------------------------------------------
extern "C" void kernel_launch(void* const* d_in, const int* in_sizes, int n_in,
                              void* d_out, int out_size) {
    const float* cross = (const float*)d_in[0];
    const float* emb   = (const float*)d_in[1];
    const float* W_ih  = (const float*)d_in[2];
    const float* W_hh  = (const float*)d_in[3];
    const float* b_ih  = (const float*)d_in[4];
    const float* b_hh  = (const float*)d_in[5];

    static int attr_done = 0;
    if (!attr_done) {
        cudaFuncSetAttribute(lstm_kernel,
                             cudaFuncAttributeMaxDynamicSharedMemorySize,
                             SMEM_BYTES);
        attr_done = 1;
    }

    xg_kernel<<<dim3(8, 10, 5), 256>>>(emb, W_ih, b_ih, b_hh, cross);

    cudaLaunchAttribute pdl[1];
    pdl[0].id = cudaLaunchAttributeProgrammaticStreamSerialization;
    pdl[0].val.programmaticStreamSerializationAllowed = 1;

    cudaLaunchConfig_t cfg1 = {};
    cfg1.gridDim = dim3(16, 8);
    cfg1.blockDim = dim3(NTHR);
    cfg1.dynamicSmemBytes = SMEM_BYTES;
    cfg1.stream = 0;
    cfg1.attrs = pdl;
    cfg1.numAttrs = 1;
    cudaLaunchKernelEx(&cfg1, lstm_kernel, W_hh);

    cudaLaunchConfig_t cfg2 = {};
    cfg2.gridDim = dim3(BB * NT * 64 / 512);
    cfg2.blockDim = dim3(256);
    cfg2.stream = 0;
    cfg2.attrs = pdl;
    cfg2.numAttrs = 1;
    cudaLaunchKernelEx(&cfg2, gather_kernel, (float4*)d_out);
}

// round 17
// speedup vs baseline: 1.3761x; 1.0236x over previous
#include <cuda_runtime.h>
#include <math.h>

typedef unsigned long long ull;

#define NT 10
#define NL 16
#define NNODES 31
#define BB 4096
#define G4 1024
#define NTHR 512
#define NKS 8                        // xg K-split factor

// lstm smem layout in floats
#define PW 260                       // W row pitch (16B aligned, conflict-free)
#define PR 80                        // sR combo pitch
#define OFF_W 0                      // 64 rows x PW
#define OFF_H (64 * PW)              // 16 warp-stages x 320 (10 combos x 32 k)
#define OFF_R (OFF_H + 16 * 320)     // 8 kslices x 20 combos x PR
#define SMEM_FLOATS (OFF_R + 8 * 20 * PR)
#define SMEM_BYTES (SMEM_FLOATS * 4)

__device__ __align__(16) float g_XG[NKS][310 * G4]; // K-eighth partials (bias on 0)
__device__ __align__(16) float g_H[2][160 * 256];
__device__ int g_src[BB * NT];                    // per-row float4 offset into H
__device__ unsigned g_flag[8 * 16 * 32];          // [cy][dx], 128B-strided

__device__ __forceinline__ float sigf(float x) { return 1.0f / (1.0f + __expf(-x)); }

__device__ __forceinline__ void fma2(ull& d, ull a, ull b) {
    asm("fma.rn.f32x2 %0, %1, %2, %0;" : "+l"(d) : "l"(a), "l"(b));
}
__device__ __forceinline__ float sum2(ull v) {
    float2 f = *(float2*)&v;
    return f.x + f.y;
}
__device__ __forceinline__ unsigned atom_add_release(unsigned* p, unsigned v) {
    unsigned r;
    asm volatile("atom.release.gpu.global.add.u32 %0, [%1], %2;"
                 : "=r"(r) : "l"(p), "r"(v) : "memory");
    return r;
}
__device__ __forceinline__ unsigned ld_acquire(unsigned* p) {
    unsigned r;
    asm volatile("ld.acquire.gpu.global.u32 %0, [%1];"
                 : "=r"(r) : "l"(p) : "memory");
    return r;
}

// ---------------------------------------------------------------------------
// xg (+fused leaf): z<8 -> XG[kz][m][j] partial GEMM over k = kz*32..+31;
// z==8 -> leaf ballot + g_src precompute + flag reset (80 tail blocks).
// Grid (8 x 10 x 9), 256 thr, ~21KB smem -> 4+ blocks/SM resident.
// Inner loop k4-vectorized: e as float4 broadcasts (1 wf / node / 4k),
// w from k-major sW pitch 129 (conflict-free reads AND stores).
// ---------------------------------------------------------------------------
#define PEX 36         // sE pitch (float4-aligned: 36 % 4 == 0)
#define PWX 129        // sW pitch (k-major rows)
__global__ void __launch_bounds__(256)
xg_kernel(const float* __restrict__ emb,
          const float* __restrict__ W_ih,
          const float* __restrict__ b_ih,
          const float* __restrict__ b_hh,
          const float* __restrict__ cross) {
    __shared__ float sE[32 * PEX];       // 32 nodes x 32 k
    __shared__ float sW[32 * PWX];       // 32 k x 128 cols
    const int tid = threadIdx.x;
    const int cb = blockIdx.x;
    const int mb = blockIdx.y;
    const int kz = blockIdx.z;
    const int ty = tid >> 5, tx = tid & 31;

    if (kz == NKS) {
        // ---- fused leaf: 80 blocks x 256 thr x 32 iters = 655360 elems ----
        const int chunk = mb * 8 + cb;           // 0..79
        if (chunk == 0 && tid < 128) g_flag[tid * 32] = 0;  // reset for lstm
        const int lane = tid & 31;
        #pragma unroll 4
        for (int it = 0; it < 32; ++it) {
            int gid = chunk * 8192 + it * 256 + tid;
            float v = __ldg(&cross[gid]);
            unsigned m = __ballot_sync(0xffffffffu, v > 0.5f);
            unsigned m16 = (m >> (lane & 16)) & 0xFFFFu;
            if ((lane & 15) == 0) {
                int row = gid >> 4;
                int lf = __ffs(m16) - 1;
                int tr = row - (row / NT) * NT;
                g_src[row] = ((tr << 4) + lf) << 6;   // float4 index into H
            }
        }
        return;
    }

    const int k0 = kz * 32;
    float acc[4][4] = {};

    // sE: 32 nodes x 32 k = 256 float4 (one per thread).
    {
        int r = tid >> 3, q = tid & 7;
        int m = mb * 32 + r;
        float4 v = (m < 310)
                 ? *(const float4*)(emb + m * 256 + k0 + q * 4)
                 : make_float4(0.f, 0.f, 0.f, 0.f);
        *(float4*)(sE + r * PEX + q * 4) = v;
    }
    // sW transposed: 128 cols x 32 k -> sW[k][col]. Warp = 4 cols x 8 q:
    // store bank = 4q+j+cl mod 32 -> all distinct (conflict-free).
    for (int idx = tid; idx < 1024; idx += 256) {
        int cl = idx >> 3, q = idx & 7;
        float4 v = *(const float4*)(W_ih + (cb * 128 + cl) * 256 + k0 + q * 4);
        sW[(q*4+0) * PWX + cl] = v.x;
        sW[(q*4+1) * PWX + cl] = v.y;
        sW[(q*4+2) * PWX + cl] = v.z;
        sW[(q*4+3) * PWX + cl] = v.w;
    }
    __syncthreads();

    #pragma unroll
    for (int k4 = 0; k4 < 8; ++k4) {
        float4 e0 = *(const float4*)(sE + (ty*4+0) * PEX + k4 * 4);
        float4 e1 = *(const float4*)(sE + (ty*4+1) * PEX + k4 * 4);
        float4 e2 = *(const float4*)(sE + (ty*4+2) * PEX + k4 * 4);
        float4 e3 = *(const float4*)(sE + (ty*4+3) * PEX + k4 * 4);
        const float* eb0 = (const float*)&e0;
        const float* eb1 = (const float*)&e1;
        const float* eb2 = (const float*)&e2;
        const float* eb3 = (const float*)&e3;
        #pragma unroll
        for (int kk = 0; kk < 4; ++kk) {
            const float* wrow = sW + (k4 * 4 + kk) * PWX;
            float w0 = wrow[tx];
            float w1 = wrow[tx + 32];
            float w2 = wrow[tx + 64];
            float w3 = wrow[tx + 96];
            float a0 = eb0[kk], a1 = eb1[kk], a2 = eb2[kk], a3 = eb3[kk];
            acc[0][0] += a0*w0; acc[0][1] += a0*w1; acc[0][2] += a0*w2; acc[0][3] += a0*w3;
            acc[1][0] += a1*w0; acc[1][1] += a1*w1; acc[1][2] += a1*w2; acc[1][3] += a1*w3;
            acc[2][0] += a2*w0; acc[2][1] += a2*w1; acc[2][2] += a2*w2; acc[2][3] += a2*w3;
            acc[3][0] += a3*w0; acc[3][1] += a3*w1; acc[3][2] += a3*w2; acc[3][3] += a3*w3;
        }
    }

    float* dst = g_XG[kz];
    #pragma unroll
    for (int i = 0; i < 4; ++i) {
        int m = mb * 32 + ty * 4 + i;
        if (m >= 310) break;
        #pragma unroll
        for (int j = 0; j < 4; ++j) {
            int col = cb * 128 + tx + 32 * j;
            float v = acc[i][j];
            if (kz == 0) v += b_ih[col] + b_hh[col];
            dst[m * G4 + col] = v;
        }
    }
}

// ---------------------------------------------------------------------------
// Persistent LSTM with P2P sync (R13-proven core). Grid (16,8), 512 thr.
// PDL: W-load overlaps xg tail; sync gates first g_XG / g_flag access.
// XG read as sum of 8 K-eighth partials (prefetched off the h-path).
// ---------------------------------------------------------------------------
__device__ __forceinline__ float xg8(const int node, const int off) {
    float s = 0.f;
    #pragma unroll
    for (int i = 0; i < NKS; ++i) s += __ldg(&g_XG[i][node * G4 + off]);
    return s;
}

__global__ void __launch_bounds__(NTHR, 1)
lstm_kernel(const float* __restrict__ W_hh) {
    extern __shared__ __align__(16) float sm[];
    float* sW = sm + OFF_W;
    float* sh = sm + OFF_H;
    float* sR = sm + OFF_R;

    const int tid = threadIdx.x;
    const int dx = blockIdx.x;      // 0..15
    const int cy = blockIdx.y;      // 0..7
    const int d0 = dx << 4;

    // Cache W_hh slice (input only — safe before the PDL sync point).
    for (int i = tid; i < 4096; i += NTHR) {
        int row = i >> 6, q = i & 63;
        int j = ((row >> 4) << 8) + d0 + (row & 15);
        *(float4*)(sW + row * PW + q * 4) = ((const float4*)W_hh)[j * 64 + q];
    }

    cudaGridDependencySynchronize();   // wait for xg (+leaf/flag-reset)

    const int lc = tid >> 4, dl = tid & 15;
    const int c = cy * 20 + lc;
    const int d = d0 + dl;
    const int tree = c >> 4, leaf = c & 15;
    unsigned* myflag = &g_flag[(cy * 16 + dx) * 32];

    // ---- Step 0 (h0 = c0 = 0) ----
    float cst = 0.f;
    if (tid < 320) {
        const int node = tree * NNODES;
        float gi = xg8(node, d);
        float gg = xg8(node, 512 + d);
        float go = xg8(node, 768 + d);
        cst = sigf(gi) * tanhf(gg);
        float h = sigf(go) * tanhf(cst);
        __stcg(&g_H[0][c * 256 + d], h);
    }
    __syncthreads();
    if (tid == 0) atom_add_release(myflag, 1);   // h generation 1 available

    const int w = tid >> 5, lane = tid & 31;
    const int cs = w & 1;            // combo half: combos cs*10..+9
    const int ks = w >> 1;           // K slice: k = ks*32..+31 (8 slices)
    const float* Wra = sW + lane * PW + ks * 32;
    const float* Wrb = sW + (lane + 32) * PW + ks * 32;
    float* hstage = sh + (cs * 8 + ks) * 320;    // warp-private h stage
    float* rb = sR + ks * (20 * PR) + cs * 10 * PR;
    unsigned* pf = &g_flag[(cy * 16 + 2 * ks + (lane & 1)) * 32];  // lanes 0/1 poll

    #pragma unroll
    for (int t = 1; t <= 4; ++t) {
        const int bin = 1 - (t & 1), bout = t & 1;

        // Prefetch this step's XG contribution (independent of h).
        float pa0 = 0.f, pa1 = 0.f, pa2 = 0.f, pa3 = 0.f;
        if (tid < 320) {
            int node = tree * NNODES + ((1 << t) - 1) + (leaf >> (4 - t));
            pa0 = xg8(node, d);
            pa1 = xg8(node, 256 + d);
            pa2 = xg8(node, 512 + d);
            pa3 = xg8(node, 768 + d);
        }

        // Wait for my 2 producer blocks only, then pull my 10x32 h slice.
        if (lane < 2) {
            while ((int)ld_acquire(pf) < t) {}
        }
        __syncwarp();
        #pragma unroll
        for (int i = 0; i < 10; ++i)
            hstage[i * 32 + lane] =
                __ldcg(&g_H[bin][(cy * 20 + cs * 10 + i) * 256 + ks * 32 + lane]);
        __syncwarp();

        ull accA[10] = {};
        ull accB[10] = {};
        #pragma unroll
        for (int kq = 0; kq < 8; ++kq) {
            ulonglong2 wa = *(const ulonglong2*)(Wra + kq * 4);
            ulonglong2 wb = *(const ulonglong2*)(Wrb + kq * 4);
            #pragma unroll
            for (int i = 0; i < 10; ++i) {
                ulonglong2 hv = *(const ulonglong2*)(hstage + i * 32 + kq * 4);
                fma2(accA[i], wa.x, hv.x); fma2(accA[i], wa.y, hv.y);
                fma2(accB[i], wb.x, hv.x); fma2(accB[i], wb.y, hv.y);
            }
        }
        #pragma unroll
        for (int i = 0; i < 10; ++i) {
            rb[i * PR + lane]      = sum2(accA[i]);
            rb[i * PR + lane + 32] = sum2(accB[i]);
        }
        __syncthreads();

        if (tid < 320) {
            const float* rr = sR + lc * PR + dl;
            float gi = pa0, gf = pa1, gg = pa2, go = pa3;
            #pragma unroll
            for (int kk = 0; kk < 8; ++kk) {
                gi += rr[kk * 1600 +  0];
                gf += rr[kk * 1600 + 16];
                gg += rr[kk * 1600 + 32];
                go += rr[kk * 1600 + 48];
            }
            cst = sigf(gf) * cst + sigf(gi) * tanhf(gg);
            float h = sigf(go) * tanhf(cst);
            __stcg(&g_H[bout][c * 256 + d], h);
        }
        __syncthreads();
        if (t < 4 && tid == 0) atom_add_release(myflag, 1);
    }
}

// ---------------------------------------------------------------------------
// Gather: R15-proven shape (5120 blocks, 2 float4/thread, g_src offsets).
// PDL-gated on lstm completion.
// ---------------------------------------------------------------------------
__global__ void gather_kernel(float4* __restrict__ out) {
    cudaGridDependencySynchronize();   // wait for lstm
    int gid = blockIdx.x * 256 + threadIdx.x;    // 0..1310719
    int row0 = gid >> 6, q = gid & 63;
    int row1 = row0 + 20480;
    int off0 = __ldg(&g_src[row0]);
    int off1 = __ldg(&g_src[row1]);
    const float4* H4 = (const float4*)g_H[0];
    float4 v0 = __ldg(H4 + off0 + q);
    float4 v1 = __ldg(H4 + off1 + q);
    out[(size_t)row0 * 64 + q] = v0;
    out[(size_t)row1 * 64 + q] = v1;
}

// ---------------------------------------------------------------------------
extern "C" void kernel_launch(void* const* d_in, const int* in_sizes, int n_in,
                              void* d_out, int out_size) {
    const float* cross = (const float*)d_in[0];
    const float* emb   = (const float*)d_in[1];
    const float* W_ih  = (const float*)d_in[2];
    const float* W_hh  = (const float*)d_in[3];
    const float* b_ih  = (const float*)d_in[4];
    const float* b_hh  = (const float*)d_in[5];

    static int attr_done = 0;
    if (!attr_done) {
        cudaFuncSetAttribute(lstm_kernel,
                             cudaFuncAttributeMaxDynamicSharedMemorySize,
                             SMEM_BYTES);
        attr_done = 1;
    }

    xg_kernel<<<dim3(8, 10, NKS + 1), 256>>>(emb, W_ih, b_ih, b_hh, cross);

    cudaLaunchAttribute pdl[1];
    pdl[0].id = cudaLaunchAttributeProgrammaticStreamSerialization;
    pdl[0].val.programmaticStreamSerializationAllowed = 1;

    cudaLaunchConfig_t cfg1 = {};
    cfg1.gridDim = dim3(16, 8);
    cfg1.blockDim = dim3(NTHR);
    cfg1.dynamicSmemBytes = SMEM_BYTES;
    cfg1.stream = 0;
    cfg1.attrs = pdl;
    cfg1.numAttrs = 1;
    cudaLaunchKernelEx(&cfg1, lstm_kernel, W_hh);

    cudaLaunchConfig_t cfg2 = {};
    cfg2.gridDim = dim3(BB * NT * 64 / 512);
    cfg2.blockDim = dim3(256);
    cfg2.stream = 0;
    cfg2.attrs = pdl;
    cfg2.numAttrs = 1;
    cudaLaunchKernelEx(&cfg2, gather_kernel, (float4*)d_out);
}